// round 2
// baseline (speedup 1.0000x reference)
#include <cuda_runtime.h>
#include <cuda_bf16.h>
#include <cstdint>

#define DT2 1.0e-6f

// ---------------- device scratch (no allocations allowed) ----------------
__device__ __nv_bfloat16 g_Xtb[64 * 4096];   // X transposed, bf16: [s][k]
__device__ float g_partial[4 * 4096 * 64];   // [ksplit][row][s]
__device__ unsigned char g_inv[4096];        // inv[j] = s+1 if j==x[s], else 0

static __device__ __forceinline__ uint32_t smem_u32(const void* p) {
    uint32_t a;
    asm("{ .reg .u64 t; cvta.to.shared.u64 t, %1; cvt.u32.u64 %0, t; }"
        : "=r"(a) : "l"(p));
    return a;
}

// ===================== kernel 1: transpose X -> bf16 + build inverse map =====================
__global__ __launch_bounds__(256) void ws_prep_kernel(
    const float* __restrict__ X, const int* __restrict__ xidx)
{
    __shared__ float ts[128][65];
    const int b = blockIdx.x;   // 32 blocks, each handles 128 k-rows of X
    const int tid = threadIdx.x;

    if (b == 0) {
        reinterpret_cast<int4*>(g_inv)[tid] = make_int4(0, 0, 0, 0);  // 256*16B = 4096B
    }

    const float* src = X + (size_t)b * 128 * 64;
#pragma unroll
    for (int it = 0; it < 32; it++) {
        int lin = it * 256 + tid;          // 8192 = 128 k x 64 s
        int kk = lin >> 6, s = lin & 63;
        ts[kk][s] = src[lin];
    }
    __syncthreads();
#pragma unroll
    for (int it = 0; it < 32; it++) {
        int lin = it * 256 + tid;
        int s = lin >> 7, kk = lin & 127;
        g_Xtb[(size_t)s * 4096 + b * 128 + kk] = __float2bfloat16(ts[kk][s]);
    }
    if (b == 0 && tid < 64) {
        g_inv[xidx[tid]] = (unsigned char)(tid + 1);
    }
}

// ===================== kernel 2: bf16 mma.sync GEMM =====================
// P[ksplit][row0:row0+128][0:64] = deno[row0:+128, k0:+1024] @ Xt^T chunk
// grid (32, 4): blockIdx.x = M tile, blockIdx.y = K split (1024 K each)
// 256 threads = 8 warps, warp grid 4(M) x 2(N), warp tile 32x32.
// Kc = 64 per chunk, double buffered.
//
// SMEM: A tile [128 rows][64 bf16], padded row stride 144B (72 bf16)
//       B tile [64 n][64 bf16 k], same 144B stride
static constexpr uint32_t A_STRIDE = 144;                 // bytes per row
static constexpr uint32_t ABUF = 128 * A_STRIDE;          // 18432
static constexpr uint32_t BBUF = 64 * A_STRIDE;           // 9216
static constexpr uint32_t SMEM_REQ = 2 * ABUF + 2 * BBUF; // 55296

static __device__ __forceinline__ void ldsm_x4(
    uint32_t* r, uint32_t addr)
{
    asm volatile(
        "ldmatrix.sync.aligned.m8n8.x4.shared.b16 {%0,%1,%2,%3}, [%4];"
        : "=r"(r[0]), "=r"(r[1]), "=r"(r[2]), "=r"(r[3]) : "r"(addr));
}

static __device__ __forceinline__ void mma_bf16(
    float* c, const uint32_t* a, uint32_t b0, uint32_t b1)
{
    asm volatile(
        "mma.sync.aligned.m16n8k16.row.col.f32.bf16.bf16.f32 "
        "{%0,%1,%2,%3}, {%4,%5,%6,%7}, {%8,%9}, {%0,%1,%2,%3};"
        : "+f"(c[0]), "+f"(c[1]), "+f"(c[2]), "+f"(c[3])
        : "r"(a[0]), "r"(a[1]), "r"(a[2]), "r"(a[3]), "r"(b0), "r"(b1));
}

__global__ __launch_bounds__(256, 1) void ws_gemm_kernel(const float* __restrict__ deno)
{
    extern __shared__ char sm[];
    const uint32_t smb = smem_u32(sm);

    const int tid = threadIdx.x;
    const int wid = tid >> 5;
    const int lid = tid & 31;
    const int wm = wid >> 1;          // 0..3 : warp M index
    const int wn = wid & 1;           // 0..1 : warp N index
    const int g = lid >> 2;           // group 0..7
    const int tig = lid & 3;          // thread-in-group

    const int row0 = blockIdx.x * 128;
    const int k0 = blockIdx.y * 1024;

    // staging decomposition (all threads)
    const int sa_r = tid >> 4;          // base row pair: covers r = sa_r + 16*it? no:
    // A: 2048 float4 = 128 rows x 16 f4/row; lin = it*256+tid -> r=lin>>4, c4=lin&15
    // B: 512 x 16B   = 64 n x 8 units;      lin = it*256+tid (2 iters) -> n=lin>>3, c8=lin&7

    float acc[2][4][4];
#pragma unroll
    for (int i = 0; i < 2; i++)
#pragma unroll
        for (int j = 0; j < 4; j++)
#pragma unroll
            for (int q = 0; q < 4; q++) acc[i][j][q] = 0.0f;

    // ---- prologue: stage chunk 0 ----
    {
        const int kc = k0;
#pragma unroll
        for (int it = 0; it < 8; it++) {
            int lin = it * 256 + tid;
            int r = lin >> 4, c4 = lin & 15;
            float4 v = *reinterpret_cast<const float4*>(
                deno + (size_t)(row0 + r) * 4096 + kc + c4 * 4);
            __nv_bfloat162 p0 = __float22bfloat162_rn(make_float2(v.x, v.y));
            __nv_bfloat162 p1 = __float22bfloat162_rn(make_float2(v.z, v.w));
            uint2 w;
            w.x = *reinterpret_cast<uint32_t*>(&p0);
            w.y = *reinterpret_cast<uint32_t*>(&p1);
            *reinterpret_cast<uint2*>(sm + r * A_STRIDE + c4 * 8) = w;
        }
#pragma unroll
        for (int it = 0; it < 2; it++) {
            int lin = it * 256 + tid;
            int n = lin >> 3, c8 = lin & 7;
            uint4 v = *reinterpret_cast<const uint4*>(
                g_Xtb + (size_t)n * 4096 + kc + c8 * 8);
            *reinterpret_cast<uint4*>(sm + 2 * ABUF + n * A_STRIDE + c8 * 16) = v;
        }
    }
    __syncthreads();

#pragma unroll 1
    for (int c = 0; c < 16; c++) {
        const int buf = c & 1;
        const uint32_t Ab = smb + buf * ABUF;
        const uint32_t Bb = smb + 2 * ABUF + buf * BBUF;

        // issue global loads for next chunk
        float4 aR[8];
        uint4 bR[2];
        if (c < 15) {
            const int kc = k0 + (c + 1) * 64;
#pragma unroll
            for (int it = 0; it < 8; it++) {
                int lin = it * 256 + tid;
                int r = lin >> 4, c4 = lin & 15;
                aR[it] = *reinterpret_cast<const float4*>(
                    deno + (size_t)(row0 + r) * 4096 + kc + c4 * 4);
            }
#pragma unroll
            for (int it = 0; it < 2; it++) {
                int lin = it * 256 + tid;
                int n = lin >> 3, c8 = lin & 7;
                bR[it] = *reinterpret_cast<const uint4*>(
                    g_Xtb + (size_t)n * 4096 + kc + c8 * 8);
            }
        }

        // compute chunk c: 4 k-steps of 16
#pragma unroll
        for (int ks = 0; ks < 4; ks++) {
            uint32_t af[2][4];
#pragma unroll
            for (int mf = 0; mf < 2; mf++) {
                int row = wm * 32 + mf * 16 + (lid & 7) + ((lid >> 3) & 1) * 8;
                uint32_t addr = Ab + row * A_STRIDE + ks * 32 + (lid >> 4) * 16;
                ldsm_x4(af[mf], addr);
            }
#pragma unroll
            for (int nf = 0; nf < 4; nf++) {
                int n = wn * 32 + nf * 8 + g;
                uint32_t bbase = Bb + n * A_STRIDE + ks * 32 + tig * 4;
                uint32_t b0 = *reinterpret_cast<const uint32_t*>(sm + (bbase - smb));
                uint32_t b1 = *reinterpret_cast<const uint32_t*>(sm + (bbase - smb) + 16);
                mma_bf16(acc[0][nf], af[0], b0, b1);
                mma_bf16(acc[1][nf], af[1], b0, b1);
            }
        }

        // store next chunk into other buffer
        if (c < 15) {
            const int nb = (c + 1) & 1;
            char* Abp = sm + nb * ABUF;
            char* Bbp = sm + 2 * ABUF + nb * BBUF;
#pragma unroll
            for (int it = 0; it < 8; it++) {
                int lin = it * 256 + tid;
                int r = lin >> 4, c4 = lin & 15;
                __nv_bfloat162 p0 = __float22bfloat162_rn(make_float2(aR[it].x, aR[it].y));
                __nv_bfloat162 p1 = __float22bfloat162_rn(make_float2(aR[it].z, aR[it].w));
                uint2 w;
                w.x = *reinterpret_cast<uint32_t*>(&p0);
                w.y = *reinterpret_cast<uint32_t*>(&p1);
                *reinterpret_cast<uint2*>(Abp + r * A_STRIDE + c4 * 8) = w;
            }
#pragma unroll
            for (int it = 0; it < 2; it++) {
                int lin = it * 256 + tid;
                int n = lin >> 3, c8 = lin & 7;
                *reinterpret_cast<uint4*>(Bbp + n * A_STRIDE + c8 * 16) = bR[it];
            }
        }
        __syncthreads();
    }

    // ---- epilogue: write partials (float2, 32B runs per 4 lanes = full sectors) ----
    float* Pp = g_partial + (size_t)blockIdx.y * (4096 * 64);
#pragma unroll
    for (int mf = 0; mf < 2; mf++) {
#pragma unroll
        for (int nf = 0; nf < 4; nf++) {
            int row = row0 + wm * 32 + mf * 16 + g;
            int col = wn * 32 + nf * 8 + tig * 2;
            float2 v0 = make_float2(acc[mf][nf][0], acc[mf][nf][1]);
            float2 v1 = make_float2(acc[mf][nf][2], acc[mf][nf][3]);
            *reinterpret_cast<float2*>(Pp + (size_t)row * 64 + col) = v0;
            *reinterpret_cast<float2*>(Pp + (size_t)(row + 8) * 64 + col) = v1;
        }
    }
}

// ===================== kernel 3: out = Y (+ dt^2 * sum partials at columns x) =====================
__global__ __launch_bounds__(256) void ws_copy_kernel(
    const float* __restrict__ Y, float* __restrict__ out)
{
    __shared__ unsigned char inv_s[4096];
    reinterpret_cast<int4*>(inv_s)[threadIdx.x] =
        reinterpret_cast<const int4*>(g_inv)[threadIdx.x];
    __syncthreads();

    size_t base = (size_t)blockIdx.x * 4096;
#pragma unroll
    for (int it = 0; it < 16; it++) {
        size_t idx = base + it * 256 + threadIdx.x;   // float4 index
        int row = (int)(idx >> 10);
        int c4 = (int)(idx & 1023);
        float4 v = reinterpret_cast<const float4*>(Y)[idx];
        uchar4 u = *reinterpret_cast<const uchar4*>(&inv_s[c4 * 4]);
        if (u.x | u.y | u.z | u.w) {
            int rb = row * 64;
            if (u.x) { int s = u.x - 1;
                v.x += DT2 * (g_partial[rb + s] + g_partial[262144 + rb + s]
                            + g_partial[524288 + rb + s] + g_partial[786432 + rb + s]); }
            if (u.y) { int s = u.y - 1;
                v.y += DT2 * (g_partial[rb + s] + g_partial[262144 + rb + s]
                            + g_partial[524288 + rb + s] + g_partial[786432 + rb + s]); }
            if (u.z) { int s = u.z - 1;
                v.z += DT2 * (g_partial[rb + s] + g_partial[262144 + rb + s]
                            + g_partial[524288 + rb + s] + g_partial[786432 + rb + s]); }
            if (u.w) { int s = u.w - 1;
                v.w += DT2 * (g_partial[rb + s] + g_partial[262144 + rb + s]
                            + g_partial[524288 + rb + s] + g_partial[786432 + rb + s]); }
        }
        reinterpret_cast<float4*>(out)[idx] = v;
    }
}

// ===================== launch =====================
extern "C" void kernel_launch(void* const* d_in, const int* in_sizes, int n_in,
                              void* d_out, int out_size)
{
    const float* Y    = (const float*)d_in[0];
    const float* X    = (const float*)d_in[1];
    const float* deno = (const float*)d_in[2];
    const int*   xi   = (const int*)d_in[3];
    float* out = (float*)d_out;

    cudaFuncSetAttribute(ws_gemm_kernel,
                         cudaFuncAttributeMaxDynamicSharedMemorySize, SMEM_REQ);

    ws_prep_kernel<<<32, 256>>>(X, xi);
    ws_gemm_kernel<<<dim3(32, 4), 256, SMEM_REQ>>>(deno);
    ws_copy_kernel<<<1024, 256>>>(Y, out);
}

// round 4
// speedup vs baseline: 1.2564x; 1.2564x over previous
#include <cuda_runtime.h>
#include <cuda_bf16.h>
#include <cstdint>

#define DT2 1.0e-6f

// ---------------- device scratch (no allocations allowed) ----------------
__device__ float g_partial[8 * 4096 * 64];   // [ksplit][row][s]

static __device__ __forceinline__ uint32_t smem_u32(const void* p) {
    uint32_t a;
    asm("{ .reg .u64 t; cvta.to.shared.u64 t, %1; cvt.u32.u64 %0, t; }"
        : "=r"(a) : "l"(p));
    return a;
}

// ===================== kernel 1: bf16 mma.sync GEMM =====================
// P[ksplit][row0:+128][0:64] = deno[row0:+128, k0:+512] @ X[k0:+512, 0:64]
// grid (32, 8): blockIdx.x = M tile (128 rows), blockIdx.y = K split (512 K)
// 256 threads = 8 warps, warp grid 4(M) x 2(N), warp tile 32x32.
// Kc = 64 per chunk (8 chunks), double buffered, register prefetch.
//
// SMEM: A tile [128 m][64 k bf16], row stride 144B  (ldmatrix, row-major A)
//       B tile [64 k][64 n bf16],  row stride 144B  (ldmatrix.trans, row-major B)
static constexpr uint32_t TSTRIDE = 144;                  // bytes per row
static constexpr uint32_t ABUF = 128 * TSTRIDE;           // 18432
static constexpr uint32_t BBUF = 64 * TSTRIDE;            // 9216
static constexpr uint32_t SMEM_REQ = 2 * ABUF + 2 * BBUF; // 55296

static __device__ __forceinline__ void ldsm_x4(uint32_t* r, uint32_t addr)
{
    asm volatile(
        "ldmatrix.sync.aligned.m8n8.x4.shared.b16 {%0,%1,%2,%3}, [%4];"
        : "=r"(r[0]), "=r"(r[1]), "=r"(r[2]), "=r"(r[3]) : "r"(addr));
}

static __device__ __forceinline__ void ldsm_x4_trans(uint32_t* r, uint32_t addr)
{
    asm volatile(
        "ldmatrix.sync.aligned.m8n8.x4.trans.shared.b16 {%0,%1,%2,%3}, [%4];"
        : "=r"(r[0]), "=r"(r[1]), "=r"(r[2]), "=r"(r[3]) : "r"(addr));
}

static __device__ __forceinline__ void mma_bf16(
    float* c, const uint32_t* a, uint32_t b0, uint32_t b1)
{
    asm volatile(
        "mma.sync.aligned.m16n8k16.row.col.f32.bf16.bf16.f32 "
        "{%0,%1,%2,%3}, {%4,%5,%6,%7}, {%8,%9}, {%0,%1,%2,%3};"
        : "+f"(c[0]), "+f"(c[1]), "+f"(c[2]), "+f"(c[3])
        : "r"(a[0]), "r"(a[1]), "r"(a[2]), "r"(a[3]), "r"(b0), "r"(b1));
}

static __device__ __forceinline__ uint32_t f4_to_bf16x2_lo(float a, float b) {
    __nv_bfloat162 p = __float22bfloat162_rn(make_float2(a, b));
    return *reinterpret_cast<uint32_t*>(&p);
}

__global__ __launch_bounds__(256, 2) void ws_gemm_kernel(
    const float* __restrict__ deno, const float* __restrict__ X)
{
    extern __shared__ char sm[];
    const uint32_t smb = smem_u32(sm);

    const int tid = threadIdx.x;
    const int wid = tid >> 5;
    const int lid = tid & 31;
    const int wm = wid >> 1;          // 0..3 : warp M index
    const int wn = wid & 1;           // 0..1 : warp N index
    const int g = lid >> 2;           // group 0..7
    const int tig = lid & 3;          // thread-in-group

    const int row0 = blockIdx.x * 128;
    const int k0 = blockIdx.y * 512;

    float acc[2][4][4];
#pragma unroll
    for (int i = 0; i < 2; i++)
#pragma unroll
        for (int j = 0; j < 4; j++)
#pragma unroll
            for (int q = 0; q < 4; q++) acc[i][j][q] = 0.0f;

    // staging index decomposition
    const int a_r = tid >> 4;            // +16 per iter? no: lin-based below
    // A: 2048 f4 = 128 m x 16 f4; B: 1024 f4 = 64 k x 16 f4

    // ---- prologue: stage chunk 0 into buffer 0 ----
    {
        const int kc = k0;
#pragma unroll
        for (int it = 0; it < 8; it++) {
            int lin = it * 256 + tid;
            int r = lin >> 4, c4 = lin & 15;
            float4 v = *reinterpret_cast<const float4*>(
                deno + (size_t)(row0 + r) * 4096 + kc + c4 * 4);
            uint2 w;
            w.x = f4_to_bf16x2_lo(v.x, v.y);
            w.y = f4_to_bf16x2_lo(v.z, v.w);
            *reinterpret_cast<uint2*>(sm + r * TSTRIDE + c4 * 8) = w;
        }
#pragma unroll
        for (int it = 0; it < 4; it++) {
            int lin = it * 256 + tid;
            int k = lin >> 4, f4 = lin & 15;
            float4 v = *reinterpret_cast<const float4*>(
                X + (size_t)(kc + k) * 64 + f4 * 4);
            uint2 w;
            w.x = f4_to_bf16x2_lo(v.x, v.y);
            w.y = f4_to_bf16x2_lo(v.z, v.w);
            *reinterpret_cast<uint2*>(sm + 2 * ABUF + k * TSTRIDE + f4 * 8) = w;
        }
    }
    __syncthreads();

    // precomputed fragment addresses (byte offsets within a buffer)
    // A (ldmatrix): row = wm*32 + mf*16 + (lid&7) + ((lid>>3)&1)*8, col16 = (lid>>4)*16
    const uint32_t a_off0 = (uint32_t)(wm * 32 + (lid & 7) + ((lid >> 3) & 1) * 8) * TSTRIDE
                          + (uint32_t)(lid >> 4) * 16;
    // B (ldmatrix.trans): k = (lid&7) + ((lid>>3)&1)*8, n0 = wn*32 + nf2*16 + (lid>>4)*8
    const uint32_t b_off0 = (uint32_t)((lid & 7) + ((lid >> 3) & 1) * 8) * TSTRIDE
                          + (uint32_t)(wn * 32 + (lid >> 4) * 8) * 2;

#pragma unroll 1
    for (int c = 0; c < 8; c++) {
        const int buf = c & 1;
        const uint32_t Ab = smb + buf * ABUF;
        const uint32_t Bb = smb + 2 * ABUF + buf * BBUF;

        // issue global loads for next chunk into registers
        float4 aR[8];
        float4 bR[4];
        if (c < 7) {
            const int kc = k0 + (c + 1) * 64;
#pragma unroll
            for (int it = 0; it < 8; it++) {
                int lin = it * 256 + tid;
                int r = lin >> 4, c4 = lin & 15;
                aR[it] = *reinterpret_cast<const float4*>(
                    deno + (size_t)(row0 + r) * 4096 + kc + c4 * 4);
            }
#pragma unroll
            for (int it = 0; it < 4; it++) {
                int lin = it * 256 + tid;
                int k = lin >> 4, f4 = lin & 15;
                bR[it] = *reinterpret_cast<const float4*>(
                    X + (size_t)(kc + k) * 64 + f4 * 4);
            }
        }

        // compute chunk c: 4 k-steps of 16
#pragma unroll
        for (int ks = 0; ks < 4; ks++) {
            uint32_t af[2][4];
#pragma unroll
            for (int mf = 0; mf < 2; mf++) {
                ldsm_x4(af[mf], Ab + a_off0 + (uint32_t)mf * (16 * TSTRIDE) + ks * 32);
            }
#pragma unroll
            for (int nf2 = 0; nf2 < 2; nf2++) {
                uint32_t br[4];
                ldsm_x4_trans(br, Bb + b_off0 + (uint32_t)(ks * 16) * TSTRIDE
                                   + (uint32_t)(nf2 * 16) * 2);
                mma_bf16(acc[0][nf2 * 2 + 0], af[0], br[0], br[1]);
                mma_bf16(acc[1][nf2 * 2 + 0], af[1], br[0], br[1]);
                mma_bf16(acc[0][nf2 * 2 + 1], af[0], br[2], br[3]);
                mma_bf16(acc[1][nf2 * 2 + 1], af[1], br[2], br[3]);
            }
        }

        // store next chunk into other buffer
        if (c < 7) {
            const int nb = (c + 1) & 1;
            char* Abp = sm + nb * ABUF;
            char* Bbp = sm + 2 * ABUF + nb * BBUF;
#pragma unroll
            for (int it = 0; it < 8; it++) {
                int lin = it * 256 + tid;
                int r = lin >> 4, c4 = lin & 15;
                uint2 w;
                w.x = f4_to_bf16x2_lo(aR[it].x, aR[it].y);
                w.y = f4_to_bf16x2_lo(aR[it].z, aR[it].w);
                *reinterpret_cast<uint2*>(Abp + r * TSTRIDE + c4 * 8) = w;
            }
#pragma unroll
            for (int it = 0; it < 4; it++) {
                int lin = it * 256 + tid;
                int k = lin >> 4, f4 = lin & 15;
                uint2 w;
                w.x = f4_to_bf16x2_lo(bR[it].x, bR[it].y);
                w.y = f4_to_bf16x2_lo(bR[it].z, bR[it].w);
                *reinterpret_cast<uint2*>(Bbp + k * TSTRIDE + f4 * 8) = w;
            }
        }
        __syncthreads();
    }

    // ---- epilogue: write partials (float2, 32B runs per 4 lanes) ----
    float* Pp = g_partial + (size_t)blockIdx.y * (4096 * 64);
#pragma unroll
    for (int mf = 0; mf < 2; mf++) {
#pragma unroll
        for (int nf = 0; nf < 4; nf++) {
            int row = row0 + wm * 32 + mf * 16 + g;
            int col = wn * 32 + nf * 8 + tig * 2;
            float2 v0 = make_float2(acc[mf][nf][0], acc[mf][nf][1]);
            float2 v1 = make_float2(acc[mf][nf][2], acc[mf][nf][3]);
            *reinterpret_cast<float2*>(Pp + (size_t)row * 64 + col) = v0;
            *reinterpret_cast<float2*>(Pp + (size_t)(row + 8) * 64 + col) = v1;
        }
    }
}

// ===================== kernel 2: out = Y (+ dt^2 * sum partials at columns x) =====================
__global__ __launch_bounds__(256) void ws_copy_kernel(
    const float* __restrict__ Y, const int* __restrict__ xidx,
    float* __restrict__ out)
{
    __shared__ unsigned char inv_s[4096];
    reinterpret_cast<int4*>(inv_s)[threadIdx.x] = make_int4(0, 0, 0, 0);
    __syncthreads();
    if (threadIdx.x < 64) {
        inv_s[xidx[threadIdx.x]] = (unsigned char)(threadIdx.x + 1);
    }
    __syncthreads();

    size_t base = (size_t)blockIdx.x * 4096;
#pragma unroll
    for (int it = 0; it < 16; it++) {
        size_t idx = base + it * 256 + threadIdx.x;   // float4 index
        int row = (int)(idx >> 10);
        int c4 = (int)(idx & 1023);
        float4 v = __ldcs(reinterpret_cast<const float4*>(Y) + idx);
        uchar4 u = *reinterpret_cast<const uchar4*>(&inv_s[c4 * 4]);
        if (u.x | u.y | u.z | u.w) {
            int rb = row * 64;
            if (u.x) { int s = u.x - 1; float t = 0.0f;
#pragma unroll
                for (int p = 0; p < 8; p++) t += __ldg(&g_partial[p * 262144 + rb + s]);
                v.x += DT2 * t; }
            if (u.y) { int s = u.y - 1; float t = 0.0f;
#pragma unroll
                for (int p = 0; p < 8; p++) t += __ldg(&g_partial[p * 262144 + rb + s]);
                v.y += DT2 * t; }
            if (u.z) { int s = u.z - 1; float t = 0.0f;
#pragma unroll
                for (int p = 0; p < 8; p++) t += __ldg(&g_partial[p * 262144 + rb + s]);
                v.z += DT2 * t; }
            if (u.w) { int s = u.w - 1; float t = 0.0f;
#pragma unroll
                for (int p = 0; p < 8; p++) t += __ldg(&g_partial[p * 262144 + rb + s]);
                v.w += DT2 * t; }
        }
        __stcs(reinterpret_cast<float4*>(out) + idx, v);
    }
}

// ===================== launch =====================
extern "C" void kernel_launch(void* const* d_in, const int* in_sizes, int n_in,
                              void* d_out, int out_size)
{
    const float* Y    = (const float*)d_in[0];
    const float* X    = (const float*)d_in[1];
    const float* deno = (const float*)d_in[2];
    const int*   xi   = (const int*)d_in[3];
    float* out = (float*)d_out;

    cudaFuncSetAttribute(ws_gemm_kernel,
                         cudaFuncAttributeMaxDynamicSharedMemorySize, SMEM_REQ);

    ws_gemm_kernel<<<dim3(32, 8), 256, SMEM_REQ>>>(deno, X);
    ws_copy_kernel<<<1024, 256>>>(Y, xi, out);
}

// round 5
// speedup vs baseline: 1.4533x; 1.1567x over previous
#include <cuda_runtime.h>
#include <cuda_bf16.h>
#include <cstdint>

#define DT2 1.0e-6f

// ---------------- device scratch (no allocations allowed) ----------------
__device__ float g_partial[8 * 4096 * 64];   // [ksplit][row*64+s]

static __device__ __forceinline__ uint32_t smem_u32(const void* p) {
    uint32_t a;
    asm("{ .reg .u64 t; cvta.to.shared.u64 t, %1; cvt.u32.u64 %0, t; }"
        : "=r"(a) : "l"(p));
    return a;
}

// ===================== kernel 1: bf16 mma.sync GEMM =====================
// P[ksplit][row0:+128][0:64] = deno[row0:+128, k0:+512] @ X[k0:+512, 0:64]
// grid (32, 8): blockIdx.x = M tile (128 rows), blockIdx.y = K split (512 K)
// 256 threads = 8 warps, warp grid 4(M) x 2(N), warp tile 32x32.
// Kc = 64 per chunk (8 chunks), double buffered, register prefetch.
static constexpr uint32_t TSTRIDE = 144;                  // bytes per row
static constexpr uint32_t ABUF = 128 * TSTRIDE;           // 18432
static constexpr uint32_t BBUF = 64 * TSTRIDE;            // 9216
static constexpr uint32_t SMEM_REQ = 2 * ABUF + 2 * BBUF; // 55296

static __device__ __forceinline__ void ldsm_x4(uint32_t* r, uint32_t addr)
{
    asm volatile(
        "ldmatrix.sync.aligned.m8n8.x4.shared.b16 {%0,%1,%2,%3}, [%4];"
        : "=r"(r[0]), "=r"(r[1]), "=r"(r[2]), "=r"(r[3]) : "r"(addr));
}

static __device__ __forceinline__ void ldsm_x4_trans(uint32_t* r, uint32_t addr)
{
    asm volatile(
        "ldmatrix.sync.aligned.m8n8.x4.trans.shared.b16 {%0,%1,%2,%3}, [%4];"
        : "=r"(r[0]), "=r"(r[1]), "=r"(r[2]), "=r"(r[3]) : "r"(addr));
}

static __device__ __forceinline__ void mma_bf16(
    float* c, const uint32_t* a, uint32_t b0, uint32_t b1)
{
    asm volatile(
        "mma.sync.aligned.m16n8k16.row.col.f32.bf16.bf16.f32 "
        "{%0,%1,%2,%3}, {%4,%5,%6,%7}, {%8,%9}, {%0,%1,%2,%3};"
        : "+f"(c[0]), "+f"(c[1]), "+f"(c[2]), "+f"(c[3])
        : "r"(a[0]), "r"(a[1]), "r"(a[2]), "r"(a[3]), "r"(b0), "r"(b1));
}

static __device__ __forceinline__ uint32_t f4_to_bf16x2_lo(float a, float b) {
    __nv_bfloat162 p = __float22bfloat162_rn(make_float2(a, b));
    return *reinterpret_cast<uint32_t*>(&p);
}

__global__ __launch_bounds__(256, 2) void ws_gemm_kernel(
    const float* __restrict__ deno, const float* __restrict__ X)
{
    extern __shared__ char sm[];
    const uint32_t smb = smem_u32(sm);

    const int tid = threadIdx.x;
    const int wid = tid >> 5;
    const int lid = tid & 31;
    const int wm = wid >> 1;          // 0..3 : warp M index
    const int wn = wid & 1;           // 0..1 : warp N index
    const int g = lid >> 2;           // group 0..7
    const int tig = lid & 3;          // thread-in-group

    const int row0 = blockIdx.x * 128;
    const int k0 = blockIdx.y * 512;

    float acc[2][4][4];
#pragma unroll
    for (int i = 0; i < 2; i++)
#pragma unroll
        for (int j = 0; j < 4; j++)
#pragma unroll
            for (int q = 0; q < 4; q++) acc[i][j][q] = 0.0f;

    // ---- prologue: stage chunk 0 into buffer 0 ----
    {
        const int kc = k0;
#pragma unroll
        for (int it = 0; it < 8; it++) {
            int lin = it * 256 + tid;
            int r = lin >> 4, c4 = lin & 15;
            float4 v = *reinterpret_cast<const float4*>(
                deno + (size_t)(row0 + r) * 4096 + kc + c4 * 4);
            uint2 w;
            w.x = f4_to_bf16x2_lo(v.x, v.y);
            w.y = f4_to_bf16x2_lo(v.z, v.w);
            *reinterpret_cast<uint2*>(sm + r * TSTRIDE + c4 * 8) = w;
        }
#pragma unroll
        for (int it = 0; it < 4; it++) {
            int lin = it * 256 + tid;
            int k = lin >> 4, f4 = lin & 15;
            float4 v = *reinterpret_cast<const float4*>(
                X + (size_t)(kc + k) * 64 + f4 * 4);
            uint2 w;
            w.x = f4_to_bf16x2_lo(v.x, v.y);
            w.y = f4_to_bf16x2_lo(v.z, v.w);
            *reinterpret_cast<uint2*>(sm + 2 * ABUF + k * TSTRIDE + f4 * 8) = w;
        }
    }
    __syncthreads();

    // precomputed fragment addresses (byte offsets within a buffer)
    const uint32_t a_off0 = (uint32_t)(wm * 32 + (lid & 7) + ((lid >> 3) & 1) * 8) * TSTRIDE
                          + (uint32_t)(lid >> 4) * 16;
    const uint32_t b_off0 = (uint32_t)((lid & 7) + ((lid >> 3) & 1) * 8) * TSTRIDE
                          + (uint32_t)(wn * 32 + (lid >> 4) * 8) * 2;

#pragma unroll 1
    for (int c = 0; c < 8; c++) {
        const int buf = c & 1;
        const uint32_t Ab = smb + buf * ABUF;
        const uint32_t Bb = smb + 2 * ABUF + buf * BBUF;

        // issue global loads for next chunk into registers
        float4 aR[8];
        float4 bR[4];
        if (c < 7) {
            const int kc = k0 + (c + 1) * 64;
#pragma unroll
            for (int it = 0; it < 8; it++) {
                int lin = it * 256 + tid;
                int r = lin >> 4, c4 = lin & 15;
                aR[it] = *reinterpret_cast<const float4*>(
                    deno + (size_t)(row0 + r) * 4096 + kc + c4 * 4);
            }
#pragma unroll
            for (int it = 0; it < 4; it++) {
                int lin = it * 256 + tid;
                int k = lin >> 4, f4 = lin & 15;
                bR[it] = *reinterpret_cast<const float4*>(
                    X + (size_t)(kc + k) * 64 + f4 * 4);
            }
        }

        // compute chunk c: 4 k-steps of 16
#pragma unroll
        for (int ks = 0; ks < 4; ks++) {
            uint32_t af[2][4];
#pragma unroll
            for (int mf = 0; mf < 2; mf++) {
                ldsm_x4(af[mf], Ab + a_off0 + (uint32_t)mf * (16 * TSTRIDE) + ks * 32);
            }
#pragma unroll
            for (int nf2 = 0; nf2 < 2; nf2++) {
                uint32_t br[4];
                ldsm_x4_trans(br, Bb + b_off0 + (uint32_t)(ks * 16) * TSTRIDE
                                   + (uint32_t)(nf2 * 16) * 2);
                mma_bf16(acc[0][nf2 * 2 + 0], af[0], br[0], br[1]);
                mma_bf16(acc[1][nf2 * 2 + 0], af[1], br[0], br[1]);
                mma_bf16(acc[0][nf2 * 2 + 1], af[0], br[2], br[3]);
                mma_bf16(acc[1][nf2 * 2 + 1], af[1], br[2], br[3]);
            }
        }

        // store next chunk into other buffer
        if (c < 7) {
            const int nb = (c + 1) & 1;
            char* Abp = sm + nb * ABUF;
            char* Bbp = sm + 2 * ABUF + nb * BBUF;
#pragma unroll
            for (int it = 0; it < 8; it++) {
                int lin = it * 256 + tid;
                int r = lin >> 4, c4 = lin & 15;
                uint2 w;
                w.x = f4_to_bf16x2_lo(aR[it].x, aR[it].y);
                w.y = f4_to_bf16x2_lo(aR[it].z, aR[it].w);
                *reinterpret_cast<uint2*>(Abp + r * TSTRIDE + c4 * 8) = w;
            }
#pragma unroll
            for (int it = 0; it < 4; it++) {
                int lin = it * 256 + tid;
                int k = lin >> 4, f4 = lin & 15;
                uint2 w;
                w.x = f4_to_bf16x2_lo(bR[it].x, bR[it].y);
                w.y = f4_to_bf16x2_lo(bR[it].z, bR[it].w);
                *reinterpret_cast<uint2*>(Bbp + k * TSTRIDE + f4 * 8) = w;
            }
        }
        __syncthreads();
    }

    // ---- epilogue: write partials (float2, 32B runs per 4 lanes) ----
    float* Pp = g_partial + (size_t)blockIdx.y * (4096 * 64);
#pragma unroll
    for (int mf = 0; mf < 2; mf++) {
#pragma unroll
        for (int nf = 0; nf < 4; nf++) {
            int row = row0 + wm * 32 + mf * 16 + g;
            int col = wn * 32 + nf * 8 + tig * 2;
            float2 v0 = make_float2(acc[mf][nf][0], acc[mf][nf][1]);
            float2 v1 = make_float2(acc[mf][nf][2], acc[mf][nf][3]);
            *reinterpret_cast<float2*>(Pp + (size_t)row * 64 + col) = v0;
            *reinterpret_cast<float2*>(Pp + (size_t)(row + 8) * 64 + col) = v1;
        }
    }
}

// ===================== kernel 2: scatter-add at columns x =====================
// Runs AFTER the D2D memcpy (same stream): out[r][x[s]] = Y[r][x[s]] + dt^2 * sum_p P[p][r][s]
// One thread per (row, s); partial reads fully coalesced (L2-resident).
__global__ __launch_bounds__(256) void ws_add_kernel(
    const float* __restrict__ Y, const int* __restrict__ xidx,
    float* __restrict__ out)
{
    __shared__ int xs_s[64];
    if (threadIdx.x < 64) xs_s[threadIdx.x] = xidx[threadIdx.x];
    __syncthreads();

    int gid = blockIdx.x * 256 + threadIdx.x;   // 0 .. 262143
    int row = gid >> 6;
    int s = gid & 63;

    float t = 0.0f;
#pragma unroll
    for (int p = 0; p < 8; p++) t += g_partial[p * 262144 + gid];

    size_t yi = (size_t)row * 4096 + xs_s[s];
    out[yi] = Y[yi] + DT2 * t;
}

// ===================== launch =====================
extern "C" void kernel_launch(void* const* d_in, const int* in_sizes, int n_in,
                              void* d_out, int out_size)
{
    const float* Y    = (const float*)d_in[0];
    const float* X    = (const float*)d_in[1];
    const float* deno = (const float*)d_in[2];
    const int*   xi   = (const int*)d_in[3];
    float* out = (float*)d_out;

    cudaFuncSetAttribute(ws_gemm_kernel,
                         cudaFuncAttributeMaxDynamicSharedMemorySize, SMEM_REQ);

    ws_gemm_kernel<<<dim3(32, 8), 256, SMEM_REQ>>>(deno, X);
    cudaMemcpyAsync(out, Y, (size_t)4096 * 4096 * sizeof(float),
                    cudaMemcpyDeviceToDevice);
    ws_add_kernel<<<1024, 256>>>(Y, xi, out);
}